// round 10
// baseline (speedup 1.0000x reference)
#include <cuda_runtime.h>
#include <cuda_fp16.h>
#include <cstdint>

#define D_DIM   1024
#define NKB     64
#define NITER   32
#define STAGES  4
#define BM      128
#define BN      128
#define NPA     64
#define NPB     32

#define A_KB_BYTES 4096
#define B_KB_BYTES 4096
#define STAGE_BYTES 16384
#define SMEM_DYN (1024 + STAGES * STAGE_BYTES)
#define DELTA 5e-3f

#define NSPLIT_B 256                 // B-split CTAs (bids 0..255)
#define GRID_TOT (NSPLIT_B + NPA * 40)   // 256 + 64*(8 A-split + 32 GEMM) = 2816

__device__ __align__(128) unsigned char g_A[(size_t)NPA * NKB * A_KB_BYTES];
__device__ __align__(128) unsigned char g_B[(size_t)NPB * NKB * B_KB_BYTES];
__device__ unsigned long long g_cands[(size_t)8192 * 256];
__device__ float g_einv[8192];
__device__ float g_cinv[4096];
__device__ int g_cntA[NPA];
__device__ int g_cntB[NPB];
__device__ int g_cntDone[NPA];
__device__ int g_cntPanels;

struct __align__(8) H4 { __half2 a, b; };

// ---------------- PTX helpers ----------------
__device__ __forceinline__ uint32_t smem_u32(const void* p) {
    uint32_t a;
    asm("{ .reg .u64 t; cvta.to.shared.u64 t, %1; cvt.u32.u64 %0, t; }" : "=r"(a) : "l"(p));
    return a;
}
#define MBAR_INIT(a, n) \
    asm volatile("mbarrier.init.shared.b64 [%0], %1;" :: "r"(a), "r"((uint32_t)(n)) : "memory")
#define MBAR_ARRIVE(a) \
    asm volatile("mbarrier.arrive.shared.b64 _, [%0];" :: "r"(a) : "memory")
#define MBAR_EXPECT_TX(a, b) \
    asm volatile("mbarrier.arrive.expect_tx.shared.b64 _, [%0], %1;" :: "r"(a), "r"((uint32_t)(b)) : "memory")
#define MBAR_WAIT(a, ph) do {                                                      \
    uint32_t _m = (a), _p = (ph), _d;                                              \
    asm volatile("{ .reg .pred p; mbarrier.try_wait.parity.acquire.cta.shared::cta.b64 p, [%1], %2; selp.b32 %0,1,0,p; }" \
        : "=r"(_d) : "r"(_m), "r"(_p) : "memory");                                 \
    if (!_d) {                                                                     \
        asm volatile("{ .reg .pred P; L1_%=: mbarrier.try_wait.parity.acquire.cta.shared::cta.b64 P, [%0], %1, 0x989680; @P bra.uni L2_%=; bra.uni L1_%=; L2_%=: }" \
            :: "r"(_m), "r"(_p) : "memory");                                       \
    }                                                                              \
} while (0)

__device__ __forceinline__ void bulk_g2s(uint32_t dst, const void* src,
                                         uint32_t bytes, uint32_t mbar) {
    asm volatile("cp.async.bulk.shared::cluster.global.mbarrier::complete_tx::bytes [%0], [%1], %2, [%3];"
        :: "r"(dst), "l"(src), "r"(bytes), "r"(mbar) : "memory");
}
__device__ __forceinline__ void hmma16(uint32_t* d, const uint32_t* a, const uint32_t* b) {
    asm volatile(
        "mma.sync.aligned.m16n8k16.row.col.f16.f16.f16.f16 "
        "{%0,%1}, {%2,%3,%4,%5}, {%6,%7}, {%0,%1};"
        : "+r"(d[0]), "+r"(d[1])
        : "r"(a[0]), "r"(a[1]), "r"(a[2]), "r"(a[3]), "r"(b[0]), "r"(b[1]));
}
__device__ __forceinline__ unsigned long long enc_key(float sim, int col) {
    return ((unsigned long long)__float_as_uint(sim) << 32) |
           (unsigned long long)(0xFFFFFFFFu - (unsigned)col);
}

// =================== fused kernel ===================
__global__ void __launch_bounds__(288, 2) fused_kernel(
    const float* __restrict__ emb, const float* __restrict__ cen,
    float* __restrict__ out, int twoout) {
    extern __shared__ __align__(16) unsigned char smem[];
    const int tid = threadIdx.x;
    const int wid = tid >> 5;
    const int lane = tid & 31;
    const int bid = blockIdx.x;

    // ---- role decode: [0,256) B-split; then per row panel p: 8 A-split + 32 GEMM ----
    bool isSplit, isB = false;
    int g = 0, by = 0, bx = 0;
    if (bid < NSPLIT_B) {
        isSplit = true; isB = true; g = bid;
    } else {
        const int gid = bid - NSPLIT_B;
        const int p = gid / 40;
        const int idx = gid - p * 40;
        if (idx < 8) { isSplit = true; g = p * 8 + idx; }
        else         { isSplit = false; by = p; bx = idx - 8; }
    }

    // ---------------- SPLIT role ----------------
    if (isSplit) {
        unsigned char* sh = smem;                    // 16 x 2064 staging (33 KB)
        const float* src = isB ? cen : emb;

        if (wid < 8) {
#pragma unroll
            for (int half = 0; half < 2; ++half) {
                const int lr = wid + 8 * half;       // local row 0..15
                const int row = g * 16 + lr;
                const float* p2 = src + (size_t)row * D_DIM;
                float4 f[8];
                float s = 0.f;
#pragma unroll
                for (int j = 0; j < 8; ++j) {
                    f[j] = ((const float4*)p2)[lane + 32 * j];
                    s += f[j].x * f[j].x + f[j].y * f[j].y +
                         f[j].z * f[j].z + f[j].w * f[j].w;
                }
#pragma unroll
                for (int m = 16; m >= 1; m >>= 1) s += __shfl_xor_sync(0xffffffffu, s, m);
                const float inv = 1.0f / fmaxf(sqrtf(s), 1e-12f);
                if (lane == 0) {
                    if (isB) g_cinv[row] = inv;
                    else     g_einv[row] = inv;
                }
#pragma unroll
                for (int j = 0; j < 8; ++j) {
                    H4 hv;
                    hv.a = __floats2half2_rn(f[j].x * inv, f[j].y * inv);
                    hv.b = __floats2half2_rn(f[j].z * inv, f[j].w * inv);
                    *(H4*)(sh + lr * 2064 + lane * 8 + 256 * j) = hv;
                }
            }
        }
        __syncthreads();

        if (wid < 8) {
            if (!isB) {
                const int pnl = g >> 3, mblk = g & 7;
                unsigned char* base = g_A + (size_t)pnl * NKB * A_KB_BYTES +
                                      mblk * 512 + lane * 16;
#pragma unroll
                for (int it = 0; it < 8; ++it) {
                    const int kb = it * 8 + wid;
                    uint32_t v[4];
#pragma unroll
                    for (int r = 0; r < 4; ++r) {
                        const int i  = (lane >> 2) + 8 * (r & 1);
                        const int kk = kb * 16 + (lane & 3) * 2 + 8 * (r >> 1);
                        v[r] = *(const uint32_t*)(sh + i * 2064 + kk * 2);
                    }
                    *(uint4*)(base + (size_t)kb * A_KB_BYTES) =
                        make_uint4(v[0], v[1], v[2], v[3]);
                }
            } else {
                const int pnl = g >> 3;
                const int nb_base = (g & 7) * 2;
                unsigned char* base = g_B + (size_t)pnl * NKB * B_KB_BYTES + lane * 8;
#pragma unroll
                for (int it = 0; it < 16; ++it) {
                    const int ci = it * 8 + wid;     // 0..127
                    const int kb = ci >> 1, nloc = ci & 1;
                    uint32_t v[2];
#pragma unroll
                    for (int s2 = 0; s2 < 2; ++s2) {
                        const int i  = nloc * 8 + (lane >> 2);
                        const int kk = kb * 16 + (lane & 3) * 2 + 8 * s2;
                        v[s2] = *(const uint32_t*)(sh + i * 2064 + kk * 2);
                    }
                    *(uint2*)(base + (size_t)kb * B_KB_BYTES + (nb_base + nloc) * 256) =
                        make_uint2(v[0], v[1]);
                }
            }
        }
        __syncthreads();
        if (tid == 0) {
            __threadfence();
            atomicAdd(isB ? &g_cntB[g >> 3] : &g_cntA[g >> 3], 1);
        }
        return;
    }

    // ---------------- GEMM role ----------------
    const uint32_t sbase = smem_u32(smem);
    const uint32_t mb_full  = sbase;
    const uint32_t mb_empty = sbase + 64;
    const uint32_t tiles    = sbase + 1024;

    if (tid == 0) {
#pragma unroll
        for (int s = 0; s < STAGES; ++s) {
            MBAR_INIT(mb_full + s * 8, 1);
            MBAR_INIT(mb_empty + s * 8, 8);
        }
    }
    __syncthreads();

    if (wid == 8) {
        if (lane == 0) {
            volatile int* vA = &g_cntA[by];
            volatile int* vB = &g_cntB[bx];
            while (*vA < 8) __nanosleep(64);
            while (*vB < 8) __nanosleep(64);
            __threadfence();
            asm volatile("fence.proxy.async;" ::: "memory");

            const unsigned char* aP = g_A + (size_t)by * NKB * A_KB_BYTES;
            const unsigned char* bP = g_B + (size_t)bx * NKB * B_KB_BYTES;
            for (int kt = 0; kt < NITER; ++kt) {
                const int s = kt & (STAGES - 1);
                MBAR_WAIT(mb_empty + s * 8, 1u ^ ((kt >> 2) & 1));
                MBAR_EXPECT_TX(mb_full + s * 8, STAGE_BYTES);
                const uint32_t st = tiles + s * STAGE_BYTES;
                bulk_g2s(st,        aP + (size_t)(2 * kt) * A_KB_BYTES, 2 * A_KB_BYTES,
                         mb_full + s * 8);
                bulk_g2s(st + 8192, bP + (size_t)(2 * kt) * B_KB_BYTES, 2 * B_KB_BYTES,
                         mb_full + s * 8);
            }
        }
    } else {
        const int wm = wid & 1;
        const int wn = wid >> 1;

        uint32_t acc[4][4][2];
#pragma unroll
        for (int mi = 0; mi < 4; ++mi)
#pragma unroll
            for (int ni = 0; ni < 4; ++ni) { acc[mi][ni][0] = 0u; acc[mi][ni][1] = 0u; }

        const uint32_t aoff = lane * 16;
        const uint32_t boff = lane * 8;

        for (int kt = 0; kt < NITER; ++kt) {
            const int s = kt & (STAGES - 1);
            MBAR_WAIT(mb_full + s * 8, (kt >> 2) & 1);
            const uint32_t stA = tiles + s * STAGE_BYTES;
            const uint32_t stB = stA + 8192;
#pragma unroll
            for (int s16 = 0; s16 < 2; ++s16) {
                uint32_t a[4][4], b[4][2];
#pragma unroll
                for (int mi = 0; mi < 4; ++mi) {
                    const uint32_t ad = stA + (uint32_t)(s16 * 8 + wm * 4 + mi) * 512 + aoff;
                    asm volatile("ld.shared.v4.b32 {%0,%1,%2,%3}, [%4];"
                        : "=r"(a[mi][0]), "=r"(a[mi][1]), "=r"(a[mi][2]), "=r"(a[mi][3])
                        : "r"(ad));
                }
#pragma unroll
                for (int ni = 0; ni < 4; ++ni) {
                    const uint32_t bd = stB + (uint32_t)(s16 * 16 + wn * 4 + ni) * 256 + boff;
                    asm volatile("ld.shared.v2.b32 {%0,%1}, [%2];"
                        : "=r"(b[ni][0]), "=r"(b[ni][1]) : "r"(bd));
                }
#pragma unroll
                for (int mi = 0; mi < 4; ++mi)
#pragma unroll
                    for (int ni = 0; ni < 4; ++ni)
                        hmma16(acc[mi][ni], a[mi], b[ni]);
            }
            if (lane == 0) MBAR_ARRIVE(mb_empty + s * 8);
        }

        // epilogue: clip, top-2 per (row, 32-col quarter)
        const int rowbase = by * BM + wm * 64;
        const int colbase = bx * BN + wn * 32 + (lane & 3) * 2;
#pragma unroll
        for (int mi = 0; mi < 4; ++mi) {
#pragma unroll
            for (int ih = 0; ih < 2; ++ih) {
                unsigned long long k1 = 0ULL, k2 = 0ULL;
#pragma unroll
                for (int ni = 0; ni < 4; ++ni) {
                    const __half2 hv = *(__half2*)&acc[mi][ni][ih];
                    const float s0 = fminf(fmaxf(__low2float(hv), 0.f), 1.f);
                    const float s1 = fminf(fmaxf(__high2float(hv), 0.f), 1.f);
                    const int c = colbase + ni * 8;
                    unsigned long long key = enc_key(s0, c);
                    if (key > k1) { k2 = k1; k1 = key; }
                    else if (key > k2) { k2 = key; }
                    key = enc_key(s1, c + 1);
                    if (key > k1) { k2 = k1; k1 = key; }
                    else if (key > k2) { k2 = key; }
                }
#pragma unroll
                for (int m = 1; m <= 2; m <<= 1) {
                    const unsigned long long o1 = __shfl_xor_sync(0xffffffffu, k1, m);
                    const unsigned long long o2 = __shfl_xor_sync(0xffffffffu, k2, m);
                    if (o1 > k1) { k2 = (k1 > o2) ? k1 : o2; k1 = o1; }
                    else         { k2 = (k2 > o1) ? k2 : o1; }
                }
                if ((lane & 3) == 0) {
                    const int r = rowbase + mi * 16 + ih * 8 + (lane >> 2);
                    ulonglong2 kk; kk.x = k1; kk.y = k2;
                    *(ulonglong2*)&g_cands[(size_t)r * 256 + bx * 8 + wn * 2] = kk;
                }
            }
        }
    }

    // ---------------- rescore election (last CTA of row panel) ----------------
    __shared__ int s_last;
    __shared__ unsigned long long list[8][16];
    __shared__ int lcnt[8];

    __syncthreads();
    if (tid == 0) {
        __threadfence();
        s_last = (atomicAdd(&g_cntDone[by], 1) == 31) ? 1 : 0;
    }
    __syncthreads();
    if (!s_last) return;
    __threadfence();

    if (tid == 0) {
        g_cntDone[by] = 0;
        g_cntA[by] = 0;
        if (atomicAdd(&g_cntPanels, 1) == NPA - 1) {
            g_cntPanels = 0;
#pragma unroll
            for (int i = 0; i < NPB; ++i) g_cntB[i] = 0;
        }
    }

    if (wid >= 8) return;

    for (int r = 0; r < 16; ++r) {
        const int row = by * BM + wid * 16 + r;

        unsigned long long k[8];
#pragma unroll
        for (int j = 0; j < 8; ++j)
            k[j] = g_cands[(size_t)row * 256 + j * 32 + lane];

        unsigned long long kmax = 0ULL;
#pragma unroll
        for (int j = 0; j < 8; ++j) if (k[j] > kmax) kmax = k[j];
#pragma unroll
        for (int m = 16; m >= 1; m >>= 1) {
            const unsigned long long o = __shfl_xor_sync(0xffffffffu, kmax, m);
            if (o > kmax) kmax = o;
        }
        const float smax = __uint_as_float((unsigned)(kmax >> 32));
        const float th = smax - DELTA;

        if (lane == 0) lcnt[wid] = 0;
        __syncwarp();
#pragma unroll
        for (int j = 0; j < 8; ++j) {
            if (__uint_as_float((unsigned)(k[j] >> 32)) >= th) {
                const int pos = atomicAdd(&lcnt[wid], 1);
                if (pos < 16) list[wid][pos] = k[j];
            }
        }
        __syncwarp();
        const int n = min(lcnt[wid], 16);

        float4 e[8];
        const float4* e4 = (const float4*)(emb + (size_t)row * D_DIM);
#pragma unroll
        for (int t2 = 0; t2 < 8; ++t2) e[t2] = e4[t2 * 32 + lane];
        const float einv = g_einv[row];

        unsigned long long bestk = 0ULL;
        for (int i = 0; i < n; ++i) {
            const unsigned col = 0xFFFFFFFFu - (unsigned)(list[wid][i] & 0xFFFFFFFFu);
            const float4* c4 = (const float4*)(cen + (size_t)col * D_DIM);
            float d = 0.f;
#pragma unroll
            for (int t2 = 0; t2 < 8; ++t2) {
                const float4 cv = c4[t2 * 32 + lane];
                d += e[t2].x * cv.x + e[t2].y * cv.y + e[t2].z * cv.z + e[t2].w * cv.w;
            }
#pragma unroll
            for (int m = 16; m >= 1; m >>= 1) d += __shfl_xor_sync(0xffffffffu, d, m);
            const float sim = fminf(fmaxf(d * einv * g_cinv[col], 0.f), 1.f);
            const unsigned long long key = enc_key(sim, (int)col);
            if (key > bestk) bestk = key;
        }

        if (lane == 0) {
            const float bsim = __uint_as_float((unsigned)(bestk >> 32));
            const unsigned bcol = 0xFFFFFFFFu - (unsigned)(bestk & 0xFFFFFFFFu);
            float nov = sqrtf(fmaxf(1.0f - bsim, 0.0f));
            out[row] = fminf(fmaxf(nov, 0.0f), 1.0f);
            if (twoout) out[8192 + row] = (float)bcol;
        }
    }
}

// ---------------- launch ----------------
extern "C" void kernel_launch(void* const* d_in, const int* in_sizes, int n_in,
                              void* d_out, int out_size) {
    const float* emb = (const float*)d_in[0];
    const float* cen = (const float*)d_in[1];
    const int B_ = in_sizes[0] / D_DIM;   // 8192

    cudaFuncSetAttribute(fused_kernel,
                         cudaFuncAttributeMaxDynamicSharedMemorySize, SMEM_DYN);
    const int twoout = (out_size >= 2 * B_) ? 1 : 0;
    fused_kernel<<<GRID_TOT, 288, SMEM_DYN>>>(emb, cen, (float*)d_out, twoout);
}

// round 11
// speedup vs baseline: 1.1421x; 1.1421x over previous
#include <cuda_runtime.h>
#include <cuda_fp16.h>
#include <cstdint>

#define D_DIM   1024
#define NKB     64            // 1024/16 k-blocks
#define NITER   32            // 1024/32
#define STAGES  4
#define BM      128
#define BN      256
#define NPA     64            // 8192/128 row panels
#define NPB     16            // 4096/256 col panels

#define A_KB_BYTES 4096       // 8 mblk x 512B
#define B_KB_BYTES 8192       // 32 nblk x 256B
#define STAGE_BYTES 24576     // 2 kb of A (8KB) + 2 kb of B (16KB)
#define SMEM_DYN (1024 + STAGES * STAGE_BYTES)
#define DELTA 5e-3f

__device__ __align__(128) unsigned char g_A[(size_t)NPA * NKB * A_KB_BYTES]; // 16.8 MB
__device__ __align__(128) unsigned char g_B[(size_t)NPB * NKB * B_KB_BYTES]; // 8.4 MB
__device__ unsigned long long g_cands[(size_t)8192 * 256];                    // 16 MB
__device__ float g_einv[8192];
__device__ float g_cinv[4096];

struct __align__(8) H4 { __half2 a, b; };

// ---------------- PTX helpers ----------------
__device__ __forceinline__ uint32_t smem_u32(const void* p) {
    uint32_t a;
    asm("{ .reg .u64 t; cvta.to.shared.u64 t, %1; cvt.u32.u64 %0, t; }" : "=r"(a) : "l"(p));
    return a;
}
#define MBAR_INIT(a, n) \
    asm volatile("mbarrier.init.shared.b64 [%0], %1;" :: "r"(a), "r"((uint32_t)(n)) : "memory")
#define MBAR_ARRIVE(a) \
    asm volatile("mbarrier.arrive.shared.b64 _, [%0];" :: "r"(a) : "memory")
#define MBAR_EXPECT_TX(a, b) \
    asm volatile("mbarrier.arrive.expect_tx.shared.b64 _, [%0], %1;" :: "r"(a), "r"((uint32_t)(b)) : "memory")
#define MBAR_WAIT(a, ph) do {                                                      \
    uint32_t _m = (a), _p = (ph), _d;                                              \
    asm volatile("{ .reg .pred p; mbarrier.try_wait.parity.acquire.cta.shared::cta.b64 p, [%1], %2; selp.b32 %0,1,0,p; }" \
        : "=r"(_d) : "r"(_m), "r"(_p) : "memory");                                 \
    if (!_d) {                                                                     \
        asm volatile("{ .reg .pred P; L1_%=: mbarrier.try_wait.parity.acquire.cta.shared::cta.b64 P, [%0], %1, 0x989680; @P bra.uni L2_%=; bra.uni L1_%=; L2_%=: }" \
            :: "r"(_m), "r"(_p) : "memory");                                       \
    }                                                                              \
} while (0)

__device__ __forceinline__ void bulk_g2s(uint32_t dst, const void* src,
                                         uint32_t bytes, uint32_t mbar) {
    asm volatile("cp.async.bulk.shared::cluster.global.mbarrier::complete_tx::bytes [%0], [%1], %2, [%3];"
        :: "r"(dst), "l"(src), "r"(bytes), "r"(mbar) : "memory");
}
__device__ __forceinline__ void hmma16(uint32_t* d, const uint32_t* a, const uint32_t* b) {
    asm volatile(
        "mma.sync.aligned.m16n8k16.row.col.f16.f16.f16.f16 "
        "{%0,%1}, {%2,%3,%4,%5}, {%6,%7}, {%0,%1};"
        : "+r"(d[0]), "+r"(d[1])
        : "r"(a[0]), "r"(a[1]), "r"(a[2]), "r"(a[3]), "r"(b[0]), "r"(b[1]));
}
__device__ __forceinline__ unsigned long long enc_key(float sim, int col) {
    return ((unsigned long long)__float_as_uint(sim) << 32) |
           (unsigned long long)(0xFFFFFFFFu - (unsigned)col);
}

// ---------------- split: 16 rows/block, warp-per-row norm, staged coalesced writes ----------------
__global__ void __launch_bounds__(512) split_kernel(const float* __restrict__ emb,
                                                    const float* __restrict__ cen,
                                                    int B_, int C_) {
    __shared__ __align__(16) unsigned char sh[16 * 2064];   // 33 KB
    const int t = threadIdx.x;
    const int w = t >> 5;          // warp = local row 0..15
    const int l = t & 31;

    const int nA = B_ >> 4;        // 512 A-blocks
    const bool isA = (int)blockIdx.x < nA;
    const int g = isA ? blockIdx.x : blockIdx.x - nA;   // 16-row group index
    const int row = g * 16 + w;
    const float* p = (isA ? emb : cen) + (size_t)row * D_DIM;

    float4 f[8];
    float s = 0.f;
#pragma unroll
    for (int j = 0; j < 8; ++j) {
        f[j] = ((const float4*)p)[l + 32 * j];
        s += f[j].x * f[j].x + f[j].y * f[j].y + f[j].z * f[j].z + f[j].w * f[j].w;
    }
#pragma unroll
    for (int m = 16; m >= 1; m >>= 1) s += __shfl_xor_sync(0xffffffffu, s, m);
    const float inv = 1.0f / fmaxf(sqrtf(s), 1e-12f);
    if (l == 0) {
        if (isA) g_einv[row] = inv;
        else     g_cinv[row] = inv;
    }

#pragma unroll
    for (int j = 0; j < 8; ++j) {
        H4 hv;
        hv.a = __floats2half2_rn(f[j].x * inv, f[j].y * inv);
        hv.b = __floats2half2_rn(f[j].z * inv, f[j].w * inv);
        *(H4*)(sh + w * 2064 + l * 8 + 256 * j) = hv;
    }
    __syncthreads();

    if (isA) {
        const int pnl = g >> 3, mblk = g & 7;   // 128-row panels: 8 groups each
        unsigned char* base = g_A + (size_t)pnl * NKB * A_KB_BYTES + mblk * 512 + l * 16;
#pragma unroll
        for (int it = 0; it < 4; ++it) {
            const int kb = it * 16 + w;
            uint32_t v[4];
#pragma unroll
            for (int r = 0; r < 4; ++r) {
                const int i  = (l >> 2) + 8 * (r & 1);
                const int kk = kb * 16 + (l & 3) * 2 + 8 * (r >> 1);
                v[r] = *(const uint32_t*)(sh + i * 2064 + kk * 2);
            }
            *(uint4*)(base + (size_t)kb * A_KB_BYTES) = make_uint4(v[0], v[1], v[2], v[3]);
        }
    } else {
        // BN=256 geometry: 256-col panels hold 16 groups of 16 cols
        const int pnl = g >> 4;
        const int nb_base = (g & 15) * 2;
        unsigned char* base = g_B + (size_t)pnl * NKB * B_KB_BYTES + l * 8;
#pragma unroll
        for (int it = 0; it < 8; ++it) {
            const int ci = it * 16 + w;          // 0..127
            const int kb = ci >> 1, nloc = ci & 1;
            uint32_t v[2];
#pragma unroll
            for (int s2 = 0; s2 < 2; ++s2) {
                const int i  = nloc * 8 + (l >> 2);
                const int kk = kb * 16 + (l & 3) * 2 + 8 * s2;
                v[s2] = *(const uint32_t*)(sh + i * 2064 + kk * 2);
            }
            *(uint2*)(base + (size_t)kb * B_KB_BYTES + (nb_base + nloc) * 256) =
                make_uint2(v[0], v[1]);
        }
    }
}

// ---------------- HMMA GEMM 128x256 + per-(row, 32-col quarter) top-2 ----------------
__global__ void __launch_bounds__(544, 1) gemm_kernel() {
    extern __shared__ __align__(16) unsigned char smem[];
    const uint32_t sbase = smem_u32(smem);
    const int tid = threadIdx.x;
    const int wid = tid >> 5;
    const int lane = tid & 31;

    const uint32_t mb_full  = sbase;
    const uint32_t mb_empty = sbase + 64;
    const uint32_t tiles    = sbase + 1024;

    if (tid == 0) {
#pragma unroll
        for (int s = 0; s < STAGES; ++s) {
            MBAR_INIT(mb_full + s * 8, 1);
            MBAR_INIT(mb_empty + s * 8, 16);    // 16 consumer warps
        }
    }
    __syncthreads();

    if (wid == 16) {
        if (lane == 0) {
            const unsigned char* aP = g_A + (size_t)blockIdx.y * NKB * A_KB_BYTES;
            const unsigned char* bP = g_B + (size_t)blockIdx.x * NKB * B_KB_BYTES;
            for (int kt = 0; kt < NITER; ++kt) {
                const int s = kt & (STAGES - 1);
                MBAR_WAIT(mb_empty + s * 8, 1u ^ ((kt >> 2) & 1));
                MBAR_EXPECT_TX(mb_full + s * 8, STAGE_BYTES);
                const uint32_t st = tiles + s * STAGE_BYTES;
                bulk_g2s(st,        aP + (size_t)(2 * kt) * A_KB_BYTES, 2 * A_KB_BYTES,
                         mb_full + s * 8);
                bulk_g2s(st + 8192, bP + (size_t)(2 * kt) * B_KB_BYTES, 2 * B_KB_BYTES,
                         mb_full + s * 8);
            }
        }
        return;
    }

    const int wm = wid & 1;      // M half (64 rows)
    const int wn = wid >> 1;     // N slice (32 cols), 0..7

    uint32_t acc[4][4][2];
#pragma unroll
    for (int mi = 0; mi < 4; ++mi)
#pragma unroll
        for (int ni = 0; ni < 4; ++ni) { acc[mi][ni][0] = 0u; acc[mi][ni][1] = 0u; }

    const uint32_t aoff = lane * 16;
    const uint32_t boff = lane * 8;

    for (int kt = 0; kt < NITER; ++kt) {
        const int s = kt & (STAGES - 1);
        MBAR_WAIT(mb_full + s * 8, (kt >> 2) & 1);
        const uint32_t stA = tiles + s * STAGE_BYTES;
        const uint32_t stB = stA + 8192;
#pragma unroll
        for (int s16 = 0; s16 < 2; ++s16) {
            uint32_t a[4][4], b[4][2];
#pragma unroll
            for (int mi = 0; mi < 4; ++mi) {
                const uint32_t ad = stA + (uint32_t)(s16 * 8 + wm * 4 + mi) * 512 + aoff;
                asm volatile("ld.shared.v4.b32 {%0,%1,%2,%3}, [%4];"
                    : "=r"(a[mi][0]), "=r"(a[mi][1]), "=r"(a[mi][2]), "=r"(a[mi][3])
                    : "r"(ad));
            }
#pragma unroll
            for (int ni = 0; ni < 4; ++ni) {
                const uint32_t bd = stB + (uint32_t)(s16 * 32 + wn * 4 + ni) * 256 + boff;
                asm volatile("ld.shared.v2.b32 {%0,%1}, [%2];"
                    : "=r"(b[ni][0]), "=r"(b[ni][1]) : "r"(bd));
            }
#pragma unroll
            for (int mi = 0; mi < 4; ++mi)
#pragma unroll
                for (int ni = 0; ni < 4; ++ni)
                    hmma16(acc[mi][ni], a[mi], b[ni]);
        }
        if (lane == 0) MBAR_ARRIVE(mb_empty + s * 8);
    }

    // ---- epilogue: clip, top-2 per (row, 32-col quarter) ----
    const int rowbase = blockIdx.y * BM + wm * 64;
    const int colbase = blockIdx.x * BN + wn * 32 + (lane & 3) * 2;
#pragma unroll
    for (int mi = 0; mi < 4; ++mi) {
#pragma unroll
        for (int ih = 0; ih < 2; ++ih) {
            unsigned long long k1 = 0ULL, k2 = 0ULL;
#pragma unroll
            for (int ni = 0; ni < 4; ++ni) {
                const __half2 hv = *(__half2*)&acc[mi][ni][ih];
                const float s0 = fminf(fmaxf(__low2float(hv), 0.f), 1.f);
                const float s1 = fminf(fmaxf(__high2float(hv), 0.f), 1.f);
                const int c = colbase + ni * 8;
                unsigned long long key = enc_key(s0, c);
                if (key > k1) { k2 = k1; k1 = key; }
                else if (key > k2) { k2 = key; }
                key = enc_key(s1, c + 1);
                if (key > k1) { k2 = k1; k1 = key; }
                else if (key > k2) { k2 = key; }
            }
#pragma unroll
            for (int m = 1; m <= 2; m <<= 1) {
                const unsigned long long o1 = __shfl_xor_sync(0xffffffffu, k1, m);
                const unsigned long long o2 = __shfl_xor_sync(0xffffffffu, k2, m);
                if (o1 > k1) { k2 = (k1 > o2) ? k1 : o2; k1 = o1; }
                else         { k2 = (k2 > o1) ? k2 : o1; }
            }
            if ((lane & 3) == 0) {
                const int r = rowbase + mi * 16 + ih * 8 + (lane >> 2);
                ulonglong2 kk; kk.x = k1; kk.y = k2;
                *(ulonglong2*)&g_cands[(size_t)r * 256 + blockIdx.x * 16 + wn * 2] = kk;
            }
        }
    }
}

// ---------------- rescore: exact fp32 for all in-window candidates ----------------
__global__ void __launch_bounds__(256) rescore_kernel(
    const float* __restrict__ emb, const float* __restrict__ cen,
    float* __restrict__ out, int B_, int twoout) {
    __shared__ unsigned long long list[8][16];
    __shared__ int lcnt[8];

    const int w = threadIdx.x >> 5;
    const int lane = threadIdx.x & 31;
    const int row = blockIdx.x * 8 + w;
    if (row >= B_) return;

    unsigned long long k[8];
#pragma unroll
    for (int j = 0; j < 8; ++j)
        k[j] = g_cands[(size_t)row * 256 + j * 32 + lane];

    unsigned long long kmax = 0ULL;
#pragma unroll
    for (int j = 0; j < 8; ++j) if (k[j] > kmax) kmax = k[j];
#pragma unroll
    for (int m = 16; m >= 1; m >>= 1) {
        const unsigned long long o = __shfl_xor_sync(0xffffffffu, kmax, m);
        if (o > kmax) kmax = o;
    }
    const float smax = __uint_as_float((unsigned)(kmax >> 32));
    const float th = smax - DELTA;

    if (lane == 0) lcnt[w] = 0;
    __syncwarp();
#pragma unroll
    for (int j = 0; j < 8; ++j) {
        if (__uint_as_float((unsigned)(k[j] >> 32)) >= th) {
            const int pos = atomicAdd(&lcnt[w], 1);
            if (pos < 16) list[w][pos] = k[j];
        }
    }
    __syncwarp();
    const int n = min(lcnt[w], 16);

    float4 e[8];
    const float4* e4 = (const float4*)(emb + (size_t)row * D_DIM);
#pragma unroll
    for (int t = 0; t < 8; ++t) e[t] = e4[t * 32 + lane];
    const float einv = g_einv[row];

    unsigned long long bestk = 0ULL;
    for (int i = 0; i < n; ++i) {
        const unsigned col = 0xFFFFFFFFu - (unsigned)(list[w][i] & 0xFFFFFFFFu);
        const float4* c4 = (const float4*)(cen + (size_t)col * D_DIM);
        float d = 0.f;
#pragma unroll
        for (int t = 0; t < 8; ++t) {
            const float4 cv = c4[t * 32 + lane];
            d += e[t].x * cv.x + e[t].y * cv.y + e[t].z * cv.z + e[t].w * cv.w;
        }
#pragma unroll
        for (int m = 16; m >= 1; m >>= 1) d += __shfl_xor_sync(0xffffffffu, d, m);
        const float sim = fminf(fmaxf(d * einv * g_cinv[col], 0.f), 1.f);
        const unsigned long long key = enc_key(sim, (int)col);
        if (key > bestk) bestk = key;
    }

    if (lane == 0) {
        const float bsim = __uint_as_float((unsigned)(bestk >> 32));
        const unsigned bcol = 0xFFFFFFFFu - (unsigned)(bestk & 0xFFFFFFFFu);
        float nov = sqrtf(fmaxf(1.0f - bsim, 0.0f));
        out[row] = fminf(fmaxf(nov, 0.0f), 1.0f);
        if (twoout) out[B_ + row] = (float)bcol;
    }
}

// ---------------- launch ----------------
extern "C" void kernel_launch(void* const* d_in, const int* in_sizes, int n_in,
                              void* d_out, int out_size) {
    const float* emb = (const float*)d_in[0];
    const float* cen = (const float*)d_in[1];
    const int B_ = in_sizes[0] / D_DIM;   // 8192
    const int C_ = in_sizes[1] / D_DIM;   // 4096

    split_kernel<<<(B_ + C_) / 16, 512>>>(emb, cen, B_, C_);

    cudaFuncSetAttribute(gemm_kernel,
                         cudaFuncAttributeMaxDynamicSharedMemorySize, SMEM_DYN);
    dim3 grid(C_ / BN, B_ / BM);          // 16 x 64 = 1024 CTAs
    gemm_kernel<<<grid, 544, SMEM_DYN>>>();

    const int twoout = (out_size >= 2 * B_) ? 1 : 0;
    rescore_kernel<<<(B_ + 7) / 8, 256>>>(emb, cen, (float*)d_out, B_, twoout);
}

// round 12
// speedup vs baseline: 1.2536x; 1.0977x over previous
#include <cuda_runtime.h>
#include <cuda_fp16.h>
#include <cstdint>

#define D_DIM   1024
#define NKB     64            // 1024/16 k-blocks
#define NITER   32            // 1024/32
#define STAGES  4
#define BM      128
#define BN      128
#define NPA     64            // 8192/128 row panels
#define NPB     32            // 4096/128 col panels

#define A_KB_BYTES 4096
#define B_KB_BYTES 4096
#define STAGE_BYTES 16384
#define SMEM_DYN (1024 + STAGES * STAGE_BYTES)
#define DELTA 5e-3f

__device__ __align__(128) unsigned char g_A[(size_t)NPA * NKB * A_KB_BYTES]; // 16.8 MB
__device__ __align__(128) unsigned char g_B[(size_t)NPB * NKB * B_KB_BYTES]; // 8.4 MB
__device__ unsigned long long g_cands[(size_t)8192 * 256];                    // 16 MB
__device__ float g_einv[8192];
__device__ float g_cinv[4096];

struct __align__(8) H4 { __half2 a, b; };

// ---------------- PTX helpers ----------------
__device__ __forceinline__ uint32_t smem_u32(const void* p) {
    uint32_t a;
    asm("{ .reg .u64 t; cvta.to.shared.u64 t, %1; cvt.u32.u64 %0, t; }" : "=r"(a) : "l"(p));
    return a;
}
#define MBAR_INIT(a, n) \
    asm volatile("mbarrier.init.shared.b64 [%0], %1;" :: "r"(a), "r"((uint32_t)(n)) : "memory")
#define MBAR_ARRIVE(a) \
    asm volatile("mbarrier.arrive.shared.b64 _, [%0];" :: "r"(a) : "memory")
#define MBAR_EXPECT_TX(a, b) \
    asm volatile("mbarrier.arrive.expect_tx.shared.b64 _, [%0], %1;" :: "r"(a), "r"((uint32_t)(b)) : "memory")
#define MBAR_WAIT(a, ph) do {                                                      \
    uint32_t _m = (a), _p = (ph), _d;                                              \
    asm volatile("{ .reg .pred p; mbarrier.try_wait.parity.acquire.cta.shared::cta.b64 p, [%1], %2; selp.b32 %0,1,0,p; }" \
        : "=r"(_d) : "r"(_m), "r"(_p) : "memory");                                 \
    if (!_d) {                                                                     \
        asm volatile("{ .reg .pred P; L1_%=: mbarrier.try_wait.parity.acquire.cta.shared::cta.b64 P, [%0], %1, 0x989680; @P bra.uni L2_%=; bra.uni L1_%=; L2_%=: }" \
            :: "r"(_m), "r"(_p) : "memory");                                       \
    }                                                                              \
} while (0)

__device__ __forceinline__ void bulk_g2s(uint32_t dst, const void* src,
                                         uint32_t bytes, uint32_t mbar) {
    asm volatile("cp.async.bulk.shared::cluster.global.mbarrier::complete_tx::bytes [%0], [%1], %2, [%3];"
        :: "r"(dst), "l"(src), "r"(bytes), "r"(mbar) : "memory");
}
__device__ __forceinline__ void hmma16(uint32_t* d, const uint32_t* a, const uint32_t* b) {
    asm volatile(
        "mma.sync.aligned.m16n8k16.row.col.f16.f16.f16.f16 "
        "{%0,%1}, {%2,%3,%4,%5}, {%6,%7}, {%0,%1};"
        : "+r"(d[0]), "+r"(d[1])
        : "r"(a[0]), "r"(a[1]), "r"(a[2]), "r"(a[3]), "r"(b[0]), "r"(b[1]));
}
__device__ __forceinline__ unsigned long long enc_key(float sim, int col) {
    return ((unsigned long long)__float_as_uint(sim) << 32) |
           (unsigned long long)(0xFFFFFFFFu - (unsigned)col);
}

// ---------------- split (R8-identical) ----------------
__global__ void __launch_bounds__(512) split_kernel(const float* __restrict__ emb,
                                                    const float* __restrict__ cen,
                                                    int B_, int C_) {
    __shared__ __align__(16) unsigned char sh[16 * 2064];
    const int t = threadIdx.x;
    const int w = t >> 5;
    const int l = t & 31;

    const int nA = B_ >> 4;
    const bool isA = (int)blockIdx.x < nA;
    const int g = isA ? blockIdx.x : blockIdx.x - nA;
    const int row = g * 16 + w;
    const float* p = (isA ? emb : cen) + (size_t)row * D_DIM;

    float4 f[8];
    float s = 0.f;
#pragma unroll
    for (int j = 0; j < 8; ++j) {
        f[j] = ((const float4*)p)[l + 32 * j];
        s += f[j].x * f[j].x + f[j].y * f[j].y + f[j].z * f[j].z + f[j].w * f[j].w;
    }
#pragma unroll
    for (int m = 16; m >= 1; m >>= 1) s += __shfl_xor_sync(0xffffffffu, s, m);
    const float inv = 1.0f / fmaxf(sqrtf(s), 1e-12f);
    if (l == 0) {
        if (isA) g_einv[row] = inv;
        else     g_cinv[row] = inv;
    }

#pragma unroll
    for (int j = 0; j < 8; ++j) {
        H4 hv;
        hv.a = __floats2half2_rn(f[j].x * inv, f[j].y * inv);
        hv.b = __floats2half2_rn(f[j].z * inv, f[j].w * inv);
        *(H4*)(sh + w * 2064 + l * 8 + 256 * j) = hv;
    }
    __syncthreads();

    if (isA) {
        const int pnl = g >> 3, mblk = g & 7;
        unsigned char* base = g_A + (size_t)pnl * NKB * A_KB_BYTES + mblk * 512 + l * 16;
#pragma unroll
        for (int it = 0; it < 4; ++it) {
            const int kb = it * 16 + w;
            uint32_t v[4];
#pragma unroll
            for (int r = 0; r < 4; ++r) {
                const int i  = (l >> 2) + 8 * (r & 1);
                const int kk = kb * 16 + (l & 3) * 2 + 8 * (r >> 1);
                v[r] = *(const uint32_t*)(sh + i * 2064 + kk * 2);
            }
            *(uint4*)(base + (size_t)kb * A_KB_BYTES) = make_uint4(v[0], v[1], v[2], v[3]);
        }
    } else {
        const int pnl = g >> 3;
        const int nb_base = (g & 7) * 2;
        unsigned char* base = g_B + (size_t)pnl * NKB * B_KB_BYTES + l * 8;
#pragma unroll
        for (int it = 0; it < 8; ++it) {
            const int ci = it * 16 + w;
            const int kb = ci >> 1, nloc = ci & 1;
            uint32_t v[2];
#pragma unroll
            for (int s2 = 0; s2 < 2; ++s2) {
                const int i  = nloc * 8 + (l >> 2);
                const int kk = kb * 16 + (l & 3) * 2 + 8 * s2;
                v[s2] = *(const uint32_t*)(sh + i * 2064 + kk * 2);
            }
            *(uint2*)(base + (size_t)kb * B_KB_BYTES + (nb_base + nloc) * 256) =
                make_uint2(v[0], v[1]);
        }
    }
}

// ---------------- HMMA GEMM: 4 warps x (64x64), 3 CTAs/SM ----------------
__global__ void __launch_bounds__(160, 3) gemm_kernel() {
    extern __shared__ __align__(16) unsigned char smem[];
    const uint32_t sbase = smem_u32(smem);
    const int tid = threadIdx.x;
    const int wid = tid >> 5;
    const int lane = tid & 31;

    const uint32_t mb_full  = sbase;
    const uint32_t mb_empty = sbase + 64;
    const uint32_t tiles    = sbase + 1024;

    if (tid == 0) {
#pragma unroll
        for (int s = 0; s < STAGES; ++s) {
            MBAR_INIT(mb_full + s * 8, 1);
            MBAR_INIT(mb_empty + s * 8, 4);     // 4 consumer warps
        }
    }
    __syncthreads();

    if (wid == 4) {
        if (lane == 0) {
            const unsigned char* aP = g_A + (size_t)blockIdx.y * NKB * A_KB_BYTES;
            const unsigned char* bP = g_B + (size_t)blockIdx.x * NKB * B_KB_BYTES;
            for (int kt = 0; kt < NITER; ++kt) {
                const int s = kt & (STAGES - 1);
                MBAR_WAIT(mb_empty + s * 8, 1u ^ ((kt >> 2) & 1));
                MBAR_EXPECT_TX(mb_full + s * 8, STAGE_BYTES);
                const uint32_t st = tiles + s * STAGE_BYTES;
                bulk_g2s(st,        aP + (size_t)(2 * kt) * A_KB_BYTES, 2 * A_KB_BYTES,
                         mb_full + s * 8);
                bulk_g2s(st + 8192, bP + (size_t)(2 * kt) * B_KB_BYTES, 2 * B_KB_BYTES,
                         mb_full + s * 8);
            }
        }
        return;
    }

    const int wm = wid & 1;      // M half (64 rows)
    const int wn = wid >> 1;     // N half (64 cols)

    uint32_t acc[4][8][2];
#pragma unroll
    for (int mi = 0; mi < 4; ++mi)
#pragma unroll
        for (int ni = 0; ni < 8; ++ni) { acc[mi][ni][0] = 0u; acc[mi][ni][1] = 0u; }

    const uint32_t aoff = lane * 16;
    const uint32_t boff = lane * 8;

    for (int kt = 0; kt < NITER; ++kt) {
        const int s = kt & (STAGES - 1);
        MBAR_WAIT(mb_full + s * 8, (kt >> 2) & 1);
        const uint32_t stA = tiles + s * STAGE_BYTES;
        const uint32_t stB = stA + 8192;
#pragma unroll
        for (int s16 = 0; s16 < 2; ++s16) {
            uint32_t a[4][4], b[8][2];
#pragma unroll
            for (int mi = 0; mi < 4; ++mi) {
                const uint32_t ad = stA + (uint32_t)(s16 * 8 + wm * 4 + mi) * 512 + aoff;
                asm volatile("ld.shared.v4.b32 {%0,%1,%2,%3}, [%4];"
                    : "=r"(a[mi][0]), "=r"(a[mi][1]), "=r"(a[mi][2]), "=r"(a[mi][3])
                    : "r"(ad));
            }
#pragma unroll
            for (int ni = 0; ni < 8; ++ni) {
                const uint32_t bd = stB + (uint32_t)(s16 * 16 + wn * 8 + ni) * 256 + boff;
                asm volatile("ld.shared.v2.b32 {%0,%1}, [%2];"
                    : "=r"(b[ni][0]), "=r"(b[ni][1]) : "r"(bd));
            }
#pragma unroll
            for (int mi = 0; mi < 4; ++mi)
#pragma unroll
                for (int ni = 0; ni < 8; ++ni)
                    hmma16(acc[mi][ni], a[mi], b[ni]);
        }
        if (lane == 0) MBAR_ARRIVE(mb_empty + s * 8);
    }

    // ---- epilogue: clip, top-2 per (row, 32-col quarter); warp owns 2 quarters ----
    const int rowbase = blockIdx.y * BM + wm * 64;
#pragma unroll
    for (int mi = 0; mi < 4; ++mi) {
#pragma unroll
        for (int ih = 0; ih < 2; ++ih) {
            const int r = rowbase + mi * 16 + ih * 8 + (lane >> 2);
#pragma unroll
            for (int g4 = 0; g4 < 2; ++g4) {
                const int colbase = blockIdx.x * BN + wn * 64 + g4 * 32 + (lane & 3) * 2;
                unsigned long long k1 = 0ULL, k2 = 0ULL;
#pragma unroll
                for (int n4 = 0; n4 < 4; ++n4) {
                    const int ni = g4 * 4 + n4;
                    const __half2 hv = *(__half2*)&acc[mi][ni][ih];
                    const float s0 = fminf(fmaxf(__low2float(hv), 0.f), 1.f);
                    const float s1 = fminf(fmaxf(__high2float(hv), 0.f), 1.f);
                    const int c = colbase + n4 * 8;
                    unsigned long long key = enc_key(s0, c);
                    if (key > k1) { k2 = k1; k1 = key; }
                    else if (key > k2) { k2 = key; }
                    key = enc_key(s1, c + 1);
                    if (key > k1) { k2 = k1; k1 = key; }
                    else if (key > k2) { k2 = key; }
                }
#pragma unroll
                for (int m = 1; m <= 2; m <<= 1) {
                    const unsigned long long o1 = __shfl_xor_sync(0xffffffffu, k1, m);
                    const unsigned long long o2 = __shfl_xor_sync(0xffffffffu, k2, m);
                    if (o1 > k1) { k2 = (k1 > o2) ? k1 : o2; k1 = o1; }
                    else         { k2 = (k2 > o1) ? k2 : o1; }
                }
                if ((lane & 3) == 0) {
                    ulonglong2 kk; kk.x = k1; kk.y = k2;
                    *(ulonglong2*)&g_cands[(size_t)r * 256 + blockIdx.x * 8 +
                                           (wn * 2 + g4) * 2] = kk;
                }
            }
        }
    }
}

// ---------------- rescore (R8-identical) ----------------
__global__ void __launch_bounds__(256) rescore_kernel(
    const float* __restrict__ emb, const float* __restrict__ cen,
    float* __restrict__ out, int B_, int twoout) {
    __shared__ unsigned long long list[8][16];
    __shared__ int lcnt[8];

    const int w = threadIdx.x >> 5;
    const int lane = threadIdx.x & 31;
    const int row = blockIdx.x * 8 + w;
    if (row >= B_) return;

    unsigned long long k[8];
#pragma unroll
    for (int j = 0; j < 8; ++j)
        k[j] = g_cands[(size_t)row * 256 + j * 32 + lane];

    unsigned long long kmax = 0ULL;
#pragma unroll
    for (int j = 0; j < 8; ++j) if (k[j] > kmax) kmax = k[j];
#pragma unroll
    for (int m = 16; m >= 1; m >>= 1) {
        const unsigned long long o = __shfl_xor_sync(0xffffffffu, kmax, m);
        if (o > kmax) kmax = o;
    }
    const float smax = __uint_as_float((unsigned)(kmax >> 32));
    const float th = smax - DELTA;

    if (lane == 0) lcnt[w] = 0;
    __syncwarp();
#pragma unroll
    for (int j = 0; j < 8; ++j) {
        if (__uint_as_float((unsigned)(k[j] >> 32)) >= th) {
            const int pos = atomicAdd(&lcnt[w], 1);
            if (pos < 16) list[w][pos] = k[j];
        }
    }
    __syncwarp();
    const int n = min(lcnt[w], 16);

    float4 e[8];
    const float4* e4 = (const float4*)(emb + (size_t)row * D_DIM);
#pragma unroll
    for (int t = 0; t < 8; ++t) e[t] = e4[t * 32 + lane];
    const float einv = g_einv[row];

    unsigned long long bestk = 0ULL;
    for (int i = 0; i < n; ++i) {
        const unsigned col = 0xFFFFFFFFu - (unsigned)(list[w][i] & 0xFFFFFFFFu);
        const float4* c4 = (const float4*)(cen + (size_t)col * D_DIM);
        float d = 0.f;
#pragma unroll
        for (int t = 0; t < 8; ++t) {
            const float4 cv = c4[t * 32 + lane];
            d += e[t].x * cv.x + e[t].y * cv.y + e[t].z * cv.z + e[t].w * cv.w;
        }
#pragma unroll
        for (int m = 16; m >= 1; m >>= 1) d += __shfl_xor_sync(0xffffffffu, d, m);
        const float sim = fminf(fmaxf(d * einv * g_cinv[col], 0.f), 1.f);
        const unsigned long long key = enc_key(sim, (int)col);
        if (key > bestk) bestk = key;
    }

    if (lane == 0) {
        const float bsim = __uint_as_float((unsigned)(bestk >> 32));
        const unsigned bcol = 0xFFFFFFFFu - (unsigned)(bestk & 0xFFFFFFFFu);
        float nov = sqrtf(fmaxf(1.0f - bsim, 0.0f));
        out[row] = fminf(fmaxf(nov, 0.0f), 1.0f);
        if (twoout) out[B_ + row] = (float)bcol;
    }
}

// ---------------- launch ----------------
extern "C" void kernel_launch(void* const* d_in, const int* in_sizes, int n_in,
                              void* d_out, int out_size) {
    const float* emb = (const float*)d_in[0];
    const float* cen = (const float*)d_in[1];
    const int B_ = in_sizes[0] / D_DIM;   // 8192
    const int C_ = in_sizes[1] / D_DIM;   // 4096

    split_kernel<<<(B_ + C_) / 16, 512>>>(emb, cen, B_, C_);

    cudaFuncSetAttribute(gemm_kernel,
                         cudaFuncAttributeMaxDynamicSharedMemorySize, SMEM_DYN);
    dim3 grid(C_ / BN, B_ / BM);          // 32 x 64 = 2048 CTAs
    gemm_kernel<<<grid, 160, SMEM_DYN>>>();

    const int twoout = (out_size >= 2 * B_) ? 1 : 0;
    rescore_kernel<<<(B_ + 7) / 8, 256>>>(emb, cen, (float*)d_out, B_, twoout);
}